// round 8
// baseline (speedup 1.0000x reference)
#include <cuda_runtime.h>
#include <cstdint>

// RoiDeform: output (B=2, k*k=16, cs=384, cs=384, C=3) fp32.
// All 384 output rows within a bin are identical.
// Kernel A: computes the 32 unique sampled rows, publishes per-row ready flags.
// Kernel B: 1024 single-wave blocks, each spin-waits on ITS row's flag only,
//           then broadcast-writes 12 rows with STG.128. PDL (PSS + early
//           trigger in A) lets B run concurrently with A.

#define BATCH 2
#define IMG_H 1600
#define IMG_W 1600
#define CH 3
#define KK 4
#define CS 384
#define PAD 32                     // (1600 - 384*4)/2
#define ROW_FLOATS (CS * CH)       // 1152
#define ROW_F4 (ROW_FLOATS / 4)    // 288
#define NROWS (BATCH * KK * KK)    // 32 unique rows
#define RPB 12                     // rows written per block (kernel B)
#define CHUNKS (CS / RPB)          // 32
#define THREADS_B ROW_F4           // 288 (9 warps)

__device__ __align__(16) float g_row[NROWS * ROW_FLOATS];  // 147 KB scratch
__device__ int g_flag[NROWS];                              // zero-initialized

// ---------------- Kernel A: compute 32 unique rows ----------------
__global__ __launch_bounds__(CS)
void row_compute_kernel(const float* __restrict__ img,
                        const float* __restrict__ delta_p)
{
    // Let kernel B launch immediately (PDL programmatic trigger).
    cudaTriggerProgrammaticLaunchCompletion();

    const int rowid = blockIdx.x;       // 0..31  = b*16 + bin
    const int b   = rowid >> 4;
    const int bin = rowid & 15;
    const int bi  = bin >> 2;
    const int bj  = bin & 3;
    const int s   = threadIdx.x;        // 0..383

    const float dp0 = __ldg(&delta_p[rowid * 2 + 0]);
    const float dp1 = __ldg(&delta_p[rowid * 2 + 1]);

    const float r = (float)(PAD + bi * CS + s) + dp0;
    const float c = (float)(PAD + bj * CS + s) + dp1;
    const float r0f = floorf(r);
    const float c0f = floorf(c);
    const float rf = r - r0f;
    const float cf = c - c0f;
    const int r0 = (int)r0f;
    const int c0 = (int)c0f;

    float a0 = 0.f, a1 = 0.f, a2 = 0.f;
    #pragma unroll
    for (int dr = 0; dr < 2; ++dr) {
        const int   ri = r0 + dr;
        const float wr = dr ? rf : (1.0f - rf);
        if (ri >= 0 && ri < IMG_H) {
            #pragma unroll
            for (int dc = 0; dc < 2; ++dc) {
                const int   ci = c0 + dc;
                const float wc = dc ? cf : (1.0f - cf);
                if (ci >= 0 && ci < IMG_W) {
                    const float w = wr * wc;
                    const float* p = img +
                        ((size_t)((size_t)b * IMG_H + ri) * IMG_W + ci) * CH;
                    a0 += w * __ldg(p + 0);
                    a1 += w * __ldg(p + 1);
                    a2 += w * __ldg(p + 2);
                }
            }
        }
    }
    float* dst = g_row + (size_t)rowid * ROW_FLOATS + s * 3;
    dst[0] = a0;
    dst[1] = a1;
    dst[2] = a2;

    // Publish: all of this block's row writes, then release the flag.
    __syncthreads();
    __threadfence();
    if (s == 0) {
        *(volatile int*)&g_flag[rowid] = 1;
    }
}

// ---------------- Kernel B: broadcast rows to output ----------------
__global__ __launch_bounds__(THREADS_B)
void row_broadcast_kernel(float* __restrict__ out)
{
    const int chunk = blockIdx.x;                   // 0..31
    const int bin   = blockIdx.y;                   // 0..15
    const int b     = blockIdx.z;                   // 0..1
    const int rowid = b * (KK * KK) + bin;
    const int q     = threadIdx.x;                  // 0..287

    const float4* src = reinterpret_cast<const float4*>(
                            g_row + (size_t)rowid * ROW_FLOATS) + q;
    float4* out4 = reinterpret_cast<float4*>(out) +
                   ((size_t)rowid * CS + (size_t)chunk * RPB) * ROW_F4 + q;

    // Wait only for OUR row to be published by kernel A.
    if (q == 0) {
        while (*(volatile int*)&g_flag[rowid] == 0) {
            __nanosleep(64);
        }
        __threadfence();   // acquire: order subsequent g_row reads
    }
    __syncthreads();

    const float4 v = __ldg(src);
    #pragma unroll
    for (int r = 0; r < RPB; ++r) {
        out4[(size_t)r * ROW_F4] = v;
    }
}

extern "C" void kernel_launch(void* const* d_in, const int* in_sizes, int n_in,
                              void* d_out, int out_size)
{
    const float* img = (const float*)d_in[0];
    const float* dp  = (const float*)d_in[1];
    float* out = (float*)d_out;
    (void)in_sizes; (void)n_in; (void)out_size;

    row_compute_kernel<<<NROWS, CS>>>(img, dp);

    // Kernel B with programmatic dependent launch: B's blocks launch while A
    // runs (A triggers at entry); per-row flags provide the data ordering.
    cudaLaunchConfig_t cfg = {};
    cfg.gridDim  = dim3(CHUNKS, KK * KK, BATCH);    // (32, 16, 2) = 1024
    cfg.blockDim = dim3(THREADS_B, 1, 1);
    cfg.dynamicSmemBytes = 0;
    cfg.stream = 0;
    cudaLaunchAttribute attr[1];
    attr[0].id = cudaLaunchAttributeProgrammaticStreamSerialization;
    attr[0].val.programmaticStreamSerializationAllowed = 1;
    cfg.attrs = attr;
    cfg.numAttrs = 1;
    cudaLaunchKernelEx(&cfg, row_broadcast_kernel, out);
}

// round 9
// speedup vs baseline: 1.1830x; 1.1830x over previous
#include <cuda_runtime.h>
#include <cstdint>

// RoiDeform: output (B=2, k*k=16, cs=384, cs=384, C=3) fp32.
// All 384 output rows within a bin are identical.
// Single fused kernel, 1024 blocks x 288 threads:
//   rowid = bid % 32  (leaders = bids 0..31, scheduled first -> no deadlock)
//   chunk = bid / 32  (each block writes 12 of the 384 identical rows)
// Leaders compute their bin's sampled row once into g_row, release a flag,
// then join the common broadcast path. Others spin briefly on the flag.
// Store stream (~5 TB/s effective, L2-write-path bound) is the hard floor.

#define BATCH 2
#define IMG_H 1600
#define IMG_W 1600
#define CH 3
#define KK 4
#define CS 384
#define PAD 32                     // (1600 - 384*4)/2
#define ROW_FLOATS (CS * CH)       // 1152
#define ROW_F4 (ROW_FLOATS / 4)    // 288
#define NROWS (BATCH * KK * KK)    // 32 unique rows
#define RPB 12                     // rows written per block
#define CHUNKS (CS / RPB)          // 32
#define THREADS 288                // 9 warps; 7 blocks/SM possible

__device__ __align__(16) float g_row[NROWS * ROW_FLOATS];  // 147 KB scratch
__device__ int g_flag[NROWS];                              // zero-initialized

__device__ __forceinline__ void sample_one(const float* __restrict__ img,
                                           int b, int bi, int bj, int s,
                                           float dp0, float dp1,
                                           float* __restrict__ dst)
{
    const float r = (float)(PAD + bi * CS + s) + dp0;
    const float c = (float)(PAD + bj * CS + s) + dp1;
    const float r0f = floorf(r);
    const float c0f = floorf(c);
    const float rf = r - r0f;
    const float cf = c - c0f;
    const int r0 = (int)r0f;
    const int c0 = (int)c0f;

    float a0 = 0.f, a1 = 0.f, a2 = 0.f;
    #pragma unroll
    for (int dr = 0; dr < 2; ++dr) {
        const int   ri = r0 + dr;
        const float wr = dr ? rf : (1.0f - rf);
        if (ri >= 0 && ri < IMG_H) {
            #pragma unroll
            for (int dc = 0; dc < 2; ++dc) {
                const int   ci = c0 + dc;
                const float wc = dc ? cf : (1.0f - cf);
                if (ci >= 0 && ci < IMG_W) {
                    const float w = wr * wc;
                    const float* p = img +
                        ((size_t)((size_t)b * IMG_H + ri) * IMG_W + ci) * CH;
                    a0 += w * __ldg(p + 0);
                    a1 += w * __ldg(p + 1);
                    a2 += w * __ldg(p + 2);
                }
            }
        }
    }
    dst[0] = a0;
    dst[1] = a1;
    dst[2] = a2;
}

__global__ __launch_bounds__(THREADS)
void roi_deform_fused(const float* __restrict__ img,
                      const float* __restrict__ delta_p,
                      float* __restrict__ out)
{
    const int bid   = blockIdx.x;          // 0..1023
    const int rowid = bid & (NROWS - 1);   // bid % 32
    const int chunk = bid >> 5;            // bid / 32, 0..31
    const int t     = threadIdx.x;         // 0..287

    if (chunk == 0) {
        // ---- Leader: compute this bin's sampled row once ----
        const int b   = rowid >> 4;
        const int bin = rowid & 15;
        const int bi  = bin >> 2;
        const int bj  = bin & 3;
        const float dp0 = __ldg(&delta_p[rowid * 2 + 0]);
        const float dp1 = __ldg(&delta_p[rowid * 2 + 1]);
        float* rowp = g_row + (size_t)rowid * ROW_FLOATS;

        sample_one(img, b, bi, bj, t, dp0, dp1, rowp + t * 3);
        if (t < CS - THREADS) {  // t < 96: second sample s = 288 + t
            sample_one(img, b, bi, bj, THREADS + t, dp0, dp1,
                       rowp + (THREADS + t) * 3);
        }
        __syncthreads();
        __threadfence();
        if (t == 0) {
            *(volatile int*)&g_flag[rowid] = 1;
        }
        __syncthreads();
    } else {
        // ---- Follower: wait for our row to be published ----
        if (t == 0) {
            while (*(volatile int*)&g_flag[rowid] == 0) {
                __nanosleep(32);
            }
            __threadfence();   // acquire: order subsequent g_row reads
        }
        __syncthreads();
    }

    // ---- Common broadcast: write RPB identical rows, STG.128 coalesced ----
    const float4 v = __ldg(reinterpret_cast<const float4*>(
                               g_row + (size_t)rowid * ROW_FLOATS) + t);
    float4* out4 = reinterpret_cast<float4*>(out) +
                   ((size_t)rowid * CS + (size_t)chunk * RPB) * ROW_F4 + t;
    #pragma unroll
    for (int r = 0; r < RPB; ++r) {
        out4[(size_t)r * ROW_F4] = v;
    }
}

extern "C" void kernel_launch(void* const* d_in, const int* in_sizes, int n_in,
                              void* d_out, int out_size)
{
    const float* img = (const float*)d_in[0];
    const float* dp  = (const float*)d_in[1];
    float* out = (float*)d_out;
    (void)in_sizes; (void)n_in; (void)out_size;

    roi_deform_fused<<<CHUNKS * NROWS, THREADS>>>(img, dp, out);  // 1024 blocks
}